// round 3
// baseline (speedup 1.0000x reference)
#include <cuda_runtime.h>
#include <math.h>

#define MAXN 50000
#define MAXE 800000
#define D 128
#define NLAYERS 9
#define NGRAPHS 256
#define ONE_PLUS_EPS 1.00001f

// ---------------- scratch (static device globals; no allocation) ----------------
__device__ float  g_h[MAXN * D];        // node features ping
__device__ float  g_h2[MAXN * D];       // node features pong
__device__ int    g_rowoff[MAXN + 1];   // CSR row offsets (by dst)
__device__ int    g_cursor[MAXN];       // degree histogram -> scatter cursor
__device__ int    g_srcperm[MAXE];      // src node per CSR slot
__device__ float4 g_ea4[MAXE];          // edge_attr (4 floats) permuted to CSR order
__device__ float  g_pooled[NGRAPHS * D];

// ---------------- CSR build ----------------
__global__ void zero_deg_kernel(int N) {
    int i = blockIdx.x * blockDim.x + threadIdx.x;
    if (i < N) g_cursor[i] = 0;
}

__global__ void hist_kernel(const int* __restrict__ dst, int E) {
    int e = blockIdx.x * blockDim.x + threadIdx.x;
    if (e < E) atomicAdd(&g_cursor[dst[e]], 1);
}

// single-block exclusive scan over degrees -> row offsets; resets cursor to offsets
__global__ void scan_kernel(int N) {
    __shared__ int sums[1024];
    int t = threadIdx.x;
    int chunk = (N + 1023) >> 10;
    int b0 = t * chunk;
    int b1 = min(b0 + chunk, N);
    int s = 0;
    for (int i = b0; i < b1; i++) s += g_cursor[i];
    sums[t] = s;
    __syncthreads();
    for (int off = 1; off < 1024; off <<= 1) {
        int v = (t >= off) ? sums[t - off] : 0;
        __syncthreads();
        sums[t] += v;
        __syncthreads();
    }
    int base = (t == 0) ? 0 : sums[t - 1];
    for (int i = b0; i < b1; i++) {
        int dv = g_cursor[i];
        g_rowoff[i] = base;
        g_cursor[i] = base;
        base += dv;
    }
    if (t == 1023) g_rowoff[N] = sums[1023];
}

__global__ void scatter_kernel(const int* __restrict__ src,
                               const int* __restrict__ dst,
                               const float4* __restrict__ attr4, int E) {
    int e = blockIdx.x * blockDim.x + threadIdx.x;
    if (e >= E) return;
    int d = dst[e];
    int p = atomicAdd(&g_cursor[d], 1);
    g_srcperm[p] = src[e];
    g_ea4[p] = attr4[e];
}

// ---------------- h = x @ Wv ----------------
__global__ void init_h_kernel(const float* __restrict__ x,
                              const float* __restrict__ Wv, int N) {
    __shared__ float xr[13];
    int n = blockIdx.x;
    if (n >= N) return;
    int d = threadIdx.x;  // 128
    if (d < 13) xr[d] = x[(long)n * 13 + d];
    __syncthreads();
    float s = 0.f;
#pragma unroll
    for (int k = 0; k < 13; k++) s = fmaf(xr[k], Wv[k * D + d], s);
    g_h[n * D + d] = s;
}

// ---------------- fused layer ----------------
// Per block: 64 nodes. Phase 1: warp-per-node aggregation -> A tile in smem.
// Phase 2: 64x128 GEMM (A @ W), epilogue relu(+bias) + residual -> hn.
// hp is read-only this layer (ping-pong), so cross-block gathers are race-free.
__global__ __launch_bounds__(256) void layer_kernel(const float* __restrict__ W,
                                                    const float* __restrict__ bias,
                                                    const float* __restrict__ We,
                                                    const float* __restrict__ hp,
                                                    float* __restrict__ hn,
                                                    int N) {
    __shared__ float As[D][68];    // [k][row] for 64 rows (padded)  ~34.8KB
    __shared__ float Bs[16][132];  // W k-chunk [k][col]              ~8.4KB
    int tid = threadIdx.x;
    int lane = tid & 31;
    int w = tid >> 5;  // 8 warps
    int row0 = blockIdx.x * 64;

    // ---- phase 1: aggregate, form A in smem ----
    // each lane owns dims [lane*4, lane*4+4); preload its 4x4 slice of We
    float wk[4][4];
#pragma unroll
    for (int k = 0; k < 4; k++) {
        float4 t = *(const float4*)&We[k * D + lane * 4];
        wk[k][0] = t.x; wk[k][1] = t.y; wk[k][2] = t.z; wk[k][3] = t.w;
    }

#pragma unroll
    for (int rr = 0; rr < 8; rr++) {
        int r = w + rr * 8;           // 0..63
        int row = row0 + r;
        float4 acc = make_float4(0.f, 0.f, 0.f, 0.f);
        if (row < N) {
            int e0 = g_rowoff[row];
            int e1 = g_rowoff[row + 1];
#pragma unroll 4
            for (int e = e0; e < e1; e++) {
                int s = g_srcperm[e];
                float4 a = g_ea4[e];
                float4 hs = *(const float4*)&hp[s * D + lane * 4];
                float mx = fmaf(a.x, wk[0][0], fmaf(a.y, wk[1][0], fmaf(a.z, wk[2][0], fmaf(a.w, wk[3][0], hs.x))));
                float my = fmaf(a.x, wk[0][1], fmaf(a.y, wk[1][1], fmaf(a.z, wk[2][1], fmaf(a.w, wk[3][1], hs.y))));
                float mz = fmaf(a.x, wk[0][2], fmaf(a.y, wk[1][2], fmaf(a.z, wk[2][2], fmaf(a.w, wk[3][2], hs.z))));
                float mw = fmaf(a.x, wk[0][3], fmaf(a.y, wk[1][3], fmaf(a.z, wk[2][3], fmaf(a.w, wk[3][3], hs.w))));
                acc.x += fmaxf(mx, 0.f);
                acc.y += fmaxf(my, 0.f);
                acc.z += fmaxf(mz, 0.f);
                acc.w += fmaxf(mw, 0.f);
            }
            float4 hv = *(const float4*)&hp[row * D + lane * 4];
            acc.x = fmaf(ONE_PLUS_EPS, hv.x, acc.x);
            acc.y = fmaf(ONE_PLUS_EPS, hv.y, acc.y);
            acc.z = fmaf(ONE_PLUS_EPS, hv.z, acc.z);
            acc.w = fmaf(ONE_PLUS_EPS, hv.w, acc.w);
        }
        As[lane * 4 + 0][r] = acc.x;
        As[lane * 4 + 1][r] = acc.y;
        As[lane * 4 + 2][r] = acc.z;
        As[lane * 4 + 3][r] = acc.w;
    }
    __syncthreads();

    // ---- phase 2: GEMM 64x128 = A(64x128) @ W(128x128) ----
    int tx = tid & 15;   // col group: cols [tx*8, tx*8+8)
    int ty = tid >> 4;   // row group: rows [ty*4, ty*4+4)

    float acc[4][8];
#pragma unroll
    for (int i = 0; i < 4; i++)
#pragma unroll
        for (int j = 0; j < 8; j++) acc[i][j] = 0.f;

    for (int kk = 0; kk < D; kk += 16) {
        // load Bs = W[kk..kk+16][:] : 512 float4, 2 per thread
#pragma unroll
        for (int i = 0; i < 2; i++) {
            int s = tid + i * 256;
            int k = s >> 5;
            int c4 = (s & 31) * 4;
            float4 wv = *(const float4*)&W[(kk + k) * D + c4];
            *(float4*)&Bs[k][c4] = wv;
        }
        __syncthreads();
#pragma unroll
        for (int k = 0; k < 16; k++) {
            float4 av = *(const float4*)&As[kk + k][ty * 4];
            float a[4] = {av.x, av.y, av.z, av.w};
            float b[8];
            *(float4*)&b[0] = *(const float4*)&Bs[k][tx * 8];
            *(float4*)&b[4] = *(const float4*)&Bs[k][tx * 8 + 4];
#pragma unroll
            for (int i = 0; i < 4; i++)
#pragma unroll
                for (int j = 0; j < 8; j++) acc[i][j] = fmaf(a[i], b[j], acc[i][j]);
        }
        __syncthreads();
    }

    // epilogue: hn = relu(acc + bias) + hp
    float bb[8];
    *(float4*)&bb[0] = *(const float4*)&bias[tx * 8];
    *(float4*)&bb[4] = *(const float4*)&bias[tx * 8 + 4];
#pragma unroll
    for (int i = 0; i < 4; i++) {
        int row = row0 + ty * 4 + i;
        if (row < N) {
            float4 h0 = *(const float4*)&hp[row * D + tx * 8];
            float4 h1 = *(const float4*)&hp[row * D + tx * 8 + 4];
            float4 o0, o1;
            o0.x = fmaxf(acc[i][0] + bb[0], 0.f) + h0.x;
            o0.y = fmaxf(acc[i][1] + bb[1], 0.f) + h0.y;
            o0.z = fmaxf(acc[i][2] + bb[2], 0.f) + h0.z;
            o0.w = fmaxf(acc[i][3] + bb[3], 0.f) + h0.w;
            o1.x = fmaxf(acc[i][4] + bb[4], 0.f) + h1.x;
            o1.y = fmaxf(acc[i][5] + bb[5], 0.f) + h1.y;
            o1.z = fmaxf(acc[i][6] + bb[6], 0.f) + h1.z;
            o1.w = fmaxf(acc[i][7] + bb[7], 0.f) + h1.w;
            *(float4*)&hn[row * D + tx * 8]     = o0;
            *(float4*)&hn[row * D + tx * 8 + 4] = o1;
        }
    }
}

// ---------------- mean pool per graph (batch is sorted int32) ----------------
__global__ void pool_kernel(const int* __restrict__ batch, const float* __restrict__ h, int N) {
    int g = blockIdx.x;
    int d = threadIdx.x;  // 128
    int lo = 0, hi = N;
    while (lo < hi) { int m = (lo + hi) >> 1; if (batch[m] < g) lo = m + 1; else hi = m; }
    int start = lo;
    lo = start; hi = N;
    while (lo < hi) { int m = (lo + hi) >> 1; if (batch[m] < g + 1) lo = m + 1; else hi = m; }
    int end = lo;
    float s = 0.f;
    for (int n = start; n < end; n++) s += h[n * D + d];
    float cnt = (float)(end - start);
    g_pooled[g * D + d] = s / fmaxf(cnt, 1.0f);
}

// ---------------- out = gelu(pooled @ Wh1 + bh1) @ Wh2 + bh2 ----------------
__global__ __launch_bounds__(512) void mlp_kernel(const float* __restrict__ Wh1,
                                                  const float* __restrict__ bh1,
                                                  const float* __restrict__ Wh2,
                                                  const float* __restrict__ bh2,
                                                  float* __restrict__ out) {
    int g = blockIdx.x;
    int j = threadIdx.x;  // 512
    __shared__ float p[D];
    __shared__ float red[512];
    if (j < D) p[j] = g_pooled[g * D + j];
    __syncthreads();
    float s = bh1[j];
#pragma unroll 8
    for (int k = 0; k < D; k++) s = fmaf(p[k], Wh1[k * 512 + j], s);
    float ge = 0.5f * s * (1.0f + erff(s * 0.70710678118654752f));
    red[j] = ge * Wh2[j];
    __syncthreads();
    for (int off = 256; off > 0; off >>= 1) {
        if (j < off) red[j] += red[j + off];
        __syncthreads();
    }
    if (j == 0) out[g] = red[0] + bh2[0];
}

// ---------------- launcher ----------------
extern "C" void kernel_launch(void* const* d_in, const int* in_sizes, int n_in,
                              void* d_out, int out_size) {
    const float* x     = (const float*)d_in[0];
    const int*   ei    = (const int*)d_in[1];
    const float* eattr = (const float*)d_in[2];
    const int*   batch = (const int*)d_in[3];
    const float* Wv    = (const float*)d_in[4];
    const float* We    = (const float*)d_in[5];
    const float* convw = (const float*)d_in[6];
    const float* convb = (const float*)d_in[7];
    const float* Wh1   = (const float*)d_in[8];
    const float* bh1   = (const float*)d_in[9];
    const float* Wh2   = (const float*)d_in[10];
    const float* bh2   = (const float*)d_in[11];
    float* out = (float*)d_out;

    int N = in_sizes[0] / 13;
    int E = in_sizes[2] / 4;
    int G = out_size;  // 256

    const int* src = ei;
    const int* dst = ei + E;

    // build CSR (by dst) + permuted edge_attr
    zero_deg_kernel<<<(N + 255) / 256, 256>>>(N);
    hist_kernel<<<(E + 255) / 256, 256>>>(dst, E);
    scan_kernel<<<1, 1024>>>(N);
    scatter_kernel<<<(E + 255) / 256, 256>>>(src, dst, (const float4*)eattr, E);

    // h = x @ Wv
    init_h_kernel<<<N, 128>>>(x, Wv, N);

    // resolve device-global pointers for ping-pong
    float* hA = nullptr;
    float* hB = nullptr;
    cudaGetSymbolAddress((void**)&hA, g_h);
    cudaGetSymbolAddress((void**)&hB, g_h2);

    float* hp = hA;
    float* hn = hB;
    int nblk = (N + 63) / 64;
    for (int l = 0; l < NLAYERS; l++) {
        layer_kernel<<<nblk, 256>>>(convw + (long)l * D * D, convb + (long)l * D,
                                    We, hp, hn, N);
        float* t = hp; hp = hn; hn = t;
    }

    pool_kernel<<<G, 128>>>(batch, hp, N);
    mlp_kernel<<<G, 512>>>(Wh1, bh1, Wh2, bh2, out);
}

// round 5
// speedup vs baseline: 1.2543x; 1.2543x over previous
#include <cuda_runtime.h>
#include <cuda_bf16.h>
#include <math.h>
#include <stdint.h>

#define MAXN 50000
#define MAXE 800000
#define D 128
#define NLAYERS 9
#define NGRAPHS 256
#define ONE_PLUS_EPS 1.00001f

// ---------------- scratch (static device globals; no allocation) ----------------
__device__ float  g_h[MAXN * D];
__device__ float  g_h2[MAXN * D];
__device__ float  g_aggr[MAXN * D];     // (1+eps)h + sum relu(...) per layer
__device__ int    g_rowoff[MAXN + 1];
__device__ int    g_cursor[MAXN];
__device__ int    g_srcperm[MAXE];
__device__ float4 g_ea4[MAXE];
__device__ float  g_pooled[NGRAPHS * D];
// W prepacked into mma b-fragment layout: [layer][kc(8)][nt(16)][lane(32)] = {bh0,bh1,bl0,bl1}
__device__ uint4  g_Wpk[NLAYERS * 8 * 16 * 32];

// ---------------- helpers ----------------
__device__ __forceinline__ unsigned short f2bf(float x) {
    __nv_bfloat16 b = __float2bfloat16_rn(x);
    return *(unsigned short*)&b;
}
__device__ __forceinline__ float bf2f(unsigned short u) {
    __nv_bfloat16 b = *(__nv_bfloat16*)&u;
    return __bfloat162float(b);
}
__device__ __forceinline__ uint32_t pack_hi(float a, float b) {
    return (uint32_t)f2bf(a) | ((uint32_t)f2bf(b) << 16);
}
__device__ __forceinline__ uint32_t pack_lo(float a, float b) {
    unsigned short ha = f2bf(a), hb = f2bf(b);
    return (uint32_t)f2bf(a - bf2f(ha)) | ((uint32_t)f2bf(b - bf2f(hb)) << 16);
}
__device__ __forceinline__ void mma_bf16(float* c, uint32_t a0, uint32_t a1, uint32_t a2, uint32_t a3,
                                         uint32_t b0, uint32_t b1) {
    asm volatile(
        "mma.sync.aligned.m16n8k16.row.col.f32.bf16.bf16.f32 "
        "{%0,%1,%2,%3}, {%4,%5,%6,%7}, {%8,%9}, {%0,%1,%2,%3};"
        : "+f"(c[0]), "+f"(c[1]), "+f"(c[2]), "+f"(c[3])
        : "r"(a0), "r"(a1), "r"(a2), "r"(a3), "r"(b0), "r"(b1));
}

// ---------------- CSR build ----------------
__global__ void zero_deg_kernel(int N) {
    int i = blockIdx.x * blockDim.x + threadIdx.x;
    if (i < N) g_cursor[i] = 0;
}
__global__ void hist_kernel(const int* __restrict__ dst, int E) {
    int e = blockIdx.x * blockDim.x + threadIdx.x;
    if (e < E) atomicAdd(&g_cursor[dst[e]], 1);
}
__global__ void scan_kernel(int N) {
    __shared__ int sums[1024];
    int t = threadIdx.x;
    int chunk = (N + 1023) >> 10;
    int b0 = t * chunk;
    int b1 = min(b0 + chunk, N);
    int s = 0;
    for (int i = b0; i < b1; i++) s += g_cursor[i];
    sums[t] = s;
    __syncthreads();
    for (int off = 1; off < 1024; off <<= 1) {
        int v = (t >= off) ? sums[t - off] : 0;
        __syncthreads();
        sums[t] += v;
        __syncthreads();
    }
    int base = (t == 0) ? 0 : sums[t - 1];
    for (int i = b0; i < b1; i++) {
        int dv = g_cursor[i];
        g_rowoff[i] = base;
        g_cursor[i] = base;
        base += dv;
    }
    if (t == 1023) g_rowoff[N] = sums[1023];
}
__global__ void scatter_kernel(const int* __restrict__ src, const int* __restrict__ dst,
                               const float4* __restrict__ attr4, int E) {
    int e = blockIdx.x * blockDim.x + threadIdx.x;
    if (e >= E) return;
    int d = dst[e];
    int p = atomicAdd(&g_cursor[d], 1);
    g_srcperm[p] = src[e];
    g_ea4[p] = attr4[e];
}

// ---------------- prepack conv weights into mma B-fragment layout (hi/lo bf16 split) ----------------
__global__ void prep_w_kernel(const float* __restrict__ convw) {
    int idx = blockIdx.x * blockDim.x + threadIdx.x;
    if (idx >= NLAYERS * 8 * 16 * 32) return;
    int lane = idx & 31;
    int nt = (idx >> 5) & 15;
    int kc = (idx >> 9) & 7;
    int l = idx >> 12;
    const float* W = convw + (long)l * D * D;
    int k0 = kc * 16 + (lane & 3) * 2;
    int n = nt * 8 + (lane >> 2);
    float w00 = W[(k0 + 0) * D + n];
    float w01 = W[(k0 + 1) * D + n];
    float w08 = W[(k0 + 8) * D + n];
    float w09 = W[(k0 + 9) * D + n];
    uint4 o;
    o.x = pack_hi(w00, w01);
    o.y = pack_hi(w08, w09);
    o.z = pack_lo(w00, w01);
    o.w = pack_lo(w08, w09);
    g_Wpk[idx] = o;
}

// ---------------- h = x @ Wv ----------------
__global__ void init_h_kernel(const float* __restrict__ x, const float* __restrict__ Wv, int N) {
    __shared__ float xr[13];
    int n = blockIdx.x;
    if (n >= N) return;
    int d = threadIdx.x;
    if (d < 13) xr[d] = x[(long)n * 13 + d];
    __syncthreads();
    float s = 0.f;
#pragma unroll
    for (int k = 0; k < 13; k++) s = fmaf(xr[k], Wv[k * D + d], s);
    g_h[n * D + d] = s;
}

// ---------------- aggregation: g_aggr[n] = (1+eps)h[n] + sum_{e:dst=n} relu(h[src]+attr@We) ----------------
__global__ __launch_bounds__(256) void aggr_kernel(const float* __restrict__ We,
                                                   const float* __restrict__ hp, int N) {
    int gw = (blockIdx.x * blockDim.x + threadIdx.x) >> 5;
    int lane = threadIdx.x & 31;
    if (gw >= N) return;

    float wk[4][4];
#pragma unroll
    for (int k = 0; k < 4; k++) {
        float4 t = *(const float4*)&We[k * D + lane * 4];
        wk[k][0] = t.x; wk[k][1] = t.y; wk[k][2] = t.z; wk[k][3] = t.w;
    }

    float4 acc;
    {
        float4 hv = *(const float4*)&hp[(long)gw * D + lane * 4];
        acc.x = ONE_PLUS_EPS * hv.x;
        acc.y = ONE_PLUS_EPS * hv.y;
        acc.z = ONE_PLUS_EPS * hv.z;
        acc.w = ONE_PLUS_EPS * hv.w;
    }
    int e0 = g_rowoff[gw];
    int e1 = g_rowoff[gw + 1];
#pragma unroll 4
    for (int e = e0; e < e1; e++) {
        int s = g_srcperm[e];
        float4 a = g_ea4[e];
        float4 hs = *(const float4*)&hp[(long)s * D + lane * 4];
        float mx = fmaf(a.x, wk[0][0], fmaf(a.y, wk[1][0], fmaf(a.z, wk[2][0], fmaf(a.w, wk[3][0], hs.x))));
        float my = fmaf(a.x, wk[0][1], fmaf(a.y, wk[1][1], fmaf(a.z, wk[2][1], fmaf(a.w, wk[3][1], hs.y))));
        float mz = fmaf(a.x, wk[0][2], fmaf(a.y, wk[1][2], fmaf(a.z, wk[2][2], fmaf(a.w, wk[3][2], hs.z))));
        float mw = fmaf(a.x, wk[0][3], fmaf(a.y, wk[1][3], fmaf(a.z, wk[2][3], fmaf(a.w, wk[3][3], hs.w))));
        acc.x += fmaxf(mx, 0.f);
        acc.y += fmaxf(my, 0.f);
        acc.z += fmaxf(mz, 0.f);
        acc.w += fmaxf(mw, 0.f);
    }
    *(float4*)&g_aggr[(long)gw * D + lane * 4] = acc;
}

// ---------------- node GEMM via mma.sync bf16 (3-term split), no smem ----------------
// Block: 128 rows (8 warps x 16). Warp computes 16x128 strip; 64 f32 accum regs/thread.
// hn = relu(aggr @ W + bias) + hp
__global__ __launch_bounds__(256) void gemm_mma_kernel(int l,
                                                       const float* __restrict__ bias,
                                                       const float* __restrict__ aggrA,
                                                       const float* __restrict__ hp,
                                                       float* __restrict__ hn, int N) {
    int tid = threadIdx.x;
    int wid = tid >> 5;
    int lane = tid & 31;
    int g = lane >> 2;
    int tg = lane & 3;
    int row0 = blockIdx.x * 128 + wid * 16;
    int r1 = row0 + g;
    int r2 = row0 + g + 8;
    bool v1 = r1 < N;
    bool v2 = r2 < N;

    const uint4* __restrict__ wbase = &g_Wpk[(long)l * 8 * 16 * 32 + lane];

    float acc[16][4];
#pragma unroll
    for (int nt = 0; nt < 16; nt++)
#pragma unroll
        for (int j = 0; j < 4; j++) acc[nt][j] = 0.f;

    const float* A1 = aggrA + (long)r1 * D;
    const float* A2 = aggrA + (long)r2 * D;

#pragma unroll
    for (int kc = 0; kc < 8; kc++) {
        int k0 = kc * 16 + tg * 2;
        float2 x00 = v1 ? *(const float2*)(A1 + k0)     : make_float2(0.f, 0.f);
        float2 x01 = v1 ? *(const float2*)(A1 + k0 + 8) : make_float2(0.f, 0.f);
        float2 x10 = v2 ? *(const float2*)(A2 + k0)     : make_float2(0.f, 0.f);
        float2 x11 = v2 ? *(const float2*)(A2 + k0 + 8) : make_float2(0.f, 0.f);
        uint32_t ah0 = pack_hi(x00.x, x00.y);
        uint32_t ah1 = pack_hi(x10.x, x10.y);
        uint32_t ah2 = pack_hi(x01.x, x01.y);
        uint32_t ah3 = pack_hi(x11.x, x11.y);
        uint32_t al0 = pack_lo(x00.x, x00.y);
        uint32_t al1 = pack_lo(x10.x, x10.y);
        uint32_t al2 = pack_lo(x01.x, x01.y);
        uint32_t al3 = pack_lo(x11.x, x11.y);

        const uint4* bp = wbase + (long)kc * 16 * 32;
#pragma unroll
        for (int nt = 0; nt < 16; nt++) {
            uint4 b = bp[nt * 32];
            mma_bf16(acc[nt], ah0, ah1, ah2, ah3, b.x, b.y);  // Ah @ Bh
            mma_bf16(acc[nt], ah0, ah1, ah2, ah3, b.z, b.w);  // Ah @ Bl
            mma_bf16(acc[nt], al0, al1, al2, al3, b.x, b.y);  // Al @ Bh
        }
    }

    // epilogue
#pragma unroll
    for (int nt = 0; nt < 16; nt++) {
        int c0 = nt * 8 + tg * 2;
        float2 bb = *(const float2*)&bias[c0];
        if (v1) {
            float2 h = *(const float2*)&hp[(long)r1 * D + c0];
            float2 o;
            o.x = fmaxf(acc[nt][0] + bb.x, 0.f) + h.x;
            o.y = fmaxf(acc[nt][1] + bb.y, 0.f) + h.y;
            *(float2*)&hn[(long)r1 * D + c0] = o;
        }
        if (v2) {
            float2 h = *(const float2*)&hp[(long)r2 * D + c0];
            float2 o;
            o.x = fmaxf(acc[nt][2] + bb.x, 0.f) + h.x;
            o.y = fmaxf(acc[nt][3] + bb.y, 0.f) + h.y;
            *(float2*)&hn[(long)r2 * D + c0] = o;
        }
    }
}

// ---------------- mean pool per graph (batch sorted int32) ----------------
__global__ void pool_kernel(const int* __restrict__ batch, const float* __restrict__ h, int N) {
    int g = blockIdx.x;
    int d = threadIdx.x;
    int lo = 0, hi = N;
    while (lo < hi) { int m = (lo + hi) >> 1; if (batch[m] < g) lo = m + 1; else hi = m; }
    int start = lo;
    lo = start; hi = N;
    while (lo < hi) { int m = (lo + hi) >> 1; if (batch[m] < g + 1) lo = m + 1; else hi = m; }
    int end = lo;
    float s = 0.f;
    for (int n = start; n < end; n++) s += h[(long)n * D + d];
    float cnt = (float)(end - start);
    g_pooled[g * D + d] = s / fmaxf(cnt, 1.0f);
}

// ---------------- MLP head ----------------
__global__ __launch_bounds__(512) void mlp_kernel(const float* __restrict__ Wh1,
                                                  const float* __restrict__ bh1,
                                                  const float* __restrict__ Wh2,
                                                  const float* __restrict__ bh2,
                                                  float* __restrict__ out) {
    int g = blockIdx.x;
    int j = threadIdx.x;
    __shared__ float p[D];
    __shared__ float red[512];
    if (j < D) p[j] = g_pooled[g * D + j];
    __syncthreads();
    float s = bh1[j];
#pragma unroll 8
    for (int k = 0; k < D; k++) s = fmaf(p[k], Wh1[k * 512 + j], s);
    float ge = 0.5f * s * (1.0f + erff(s * 0.70710678118654752f));
    red[j] = ge * Wh2[j];
    __syncthreads();
    for (int off = 256; off > 0; off >>= 1) {
        if (j < off) red[j] += red[j + off];
        __syncthreads();
    }
    if (j == 0) out[g] = red[0] + bh2[0];
}

// ---------------- launcher ----------------
extern "C" void kernel_launch(void* const* d_in, const int* in_sizes, int n_in,
                              void* d_out, int out_size) {
    const float* x     = (const float*)d_in[0];
    const int*   ei    = (const int*)d_in[1];
    const float* eattr = (const float*)d_in[2];
    const int*   batch = (const int*)d_in[3];
    const float* Wv    = (const float*)d_in[4];
    const float* We    = (const float*)d_in[5];
    const float* convw = (const float*)d_in[6];
    const float* convb = (const float*)d_in[7];
    const float* Wh1   = (const float*)d_in[8];
    const float* bh1   = (const float*)d_in[9];
    const float* Wh2   = (const float*)d_in[10];
    const float* bh2   = (const float*)d_in[11];
    float* out = (float*)d_out;

    int N = in_sizes[0] / 13;
    int E = in_sizes[2] / 4;
    int G = out_size;

    const int* src = ei;
    const int* dst = ei + E;

    // build CSR (by dst) + permuted edge_attr
    zero_deg_kernel<<<(N + 255) / 256, 256>>>(N);
    hist_kernel<<<(E + 255) / 256, 256>>>(dst, E);
    scan_kernel<<<1, 1024>>>(N);
    scatter_kernel<<<(E + 255) / 256, 256>>>(src, dst, (const float4*)eattr, E);

    // prepack conv weights (runs concurrently with CSR build stream order; same stream, fine)
    prep_w_kernel<<<(NLAYERS * 8 * 16 * 32 + 255) / 256, 256>>>(convw);

    // h = x @ Wv
    init_h_kernel<<<N, 128>>>(x, Wv, N);

    float* hA = nullptr;
    float* hB = nullptr;
    cudaGetSymbolAddress((void**)&hA, g_h);
    cudaGetSymbolAddress((void**)&hB, g_h2);
    float* aggrP = nullptr;
    cudaGetSymbolAddress((void**)&aggrP, g_aggr);

    float* hp = hA;
    float* hn = hB;
    int nblk = (N + 127) / 128;
    for (int l = 0; l < NLAYERS; l++) {
        aggr_kernel<<<(N * 32 + 255) / 256, 256>>>(We, hp, N);
        gemm_mma_kernel<<<nblk, 256>>>(l, convb + (long)l * D, aggrP, hp, hn, N);
        float* t = hp; hp = hn; hn = t;
    }

    pool_kernel<<<G, 128>>>(batch, hp, N);
    mlp_kernel<<<G, 512>>>(Wh1, bh1, Wh2, bh2, out);
}